// round 7
// baseline (speedup 1.0000x reference)
#include <cuda_runtime.h>
#include <cuda_bf16.h>
#include <cstdint>

// Problem constants
#define BATCH 4
#define NY 16384
#define NX 4096
#define CY 128
#define CX 256
#define DIMF 384       // CY + CX
#define C1 512
#define C2 256
#define C3 128
#define MTOT (BATCH*NY)   // 65536
#define IEPS 1e-8f
#define BN_EPS 1e-5f
#define DIMW (DIMF/2)     // 192 words per feat row

// ---------------- scratch (device globals; no runtime alloc) ----------------
__device__ uint32_t g_featH[(size_t)MTOT * DIMW];   // 50.3 MB split-hi activations L1
__device__ uint32_t g_featL[(size_t)MTOT * DIMW];   // 50.3 MB split-lo
__device__ float g_z1[(size_t)MTOT * C1];
__device__ float g_z2[(size_t)MTOT * C2];
__device__ float g_z3[(size_t)MTOT * C3];
__device__ float g_red[1792];
__device__ float g_aff[1792];
// pre-split weights (bf16x2 words, row-major [N][K/2])
__device__ uint32_t g_w1h[C1 * DIMF / 2], g_w1l[C1 * DIMF / 2];
__device__ uint32_t g_w2h[C2 * C1 / 2],  g_w2l[C2 * C1 / 2];
__device__ uint32_t g_w3h[C3 * C2 / 2],  g_w3l[C3 * C2 / 2];

// pack two floats to bf16x2 (a -> low half, b -> high half)
__device__ __forceinline__ uint32_t cvt2bf(float lo, float hi) {
    uint32_t r;
    asm("cvt.rn.bf16x2.f32 %0, %1, %2;" : "=r"(r) : "f"(hi), "f"(lo));
    return r;
}
// split pair (a=low elem, b=high elem) into hi word + residual-lo word
__device__ __forceinline__ void split2(float a, float b, uint32_t& h, uint32_t& l) {
    h = cvt2bf(a, b);
    float h0 = __uint_as_float(h << 16);
    float h1 = __uint_as_float(h & 0xffff0000u);
    l = cvt2bf(a - h0, b - h1);
}

// m16n8k16 BF16 mma
__device__ __forceinline__ void mma16(float* c, const uint32_t* a, const uint32_t* b) {
    asm volatile(
        "mma.sync.aligned.m16n8k16.row.col.f32.bf16.bf16.f32 "
        "{%0,%1,%2,%3}, {%4,%5,%6,%7}, {%8,%9}, {%0,%1,%2,%3};"
        : "+f"(c[0]), "+f"(c[1]), "+f"(c[2]), "+f"(c[3])
        : "r"(a[0]), "r"(a[1]), "r"(a[2]), "r"(a[3]),
          "r"(b[0]), "r"(b[1]));
}

// ---------------- zero kernel ----------------
__global__ void zero_kernel(float* __restrict__ p, int n) {
    int i = blockIdx.x * blockDim.x + threadIdx.x;
    if (i < n) p[i] = 0.0f;
}

// ---------------- weight split prep ----------------
__global__ void split_w_kernel(const float* __restrict__ W,
                               uint32_t* __restrict__ H, uint32_t* __restrict__ L, int nwords) {
    int i = blockIdx.x * blockDim.x + threadIdx.x;
    if (i < nwords) {
        float a = W[2 * i], b = W[2 * i + 1];
        uint32_t h, l;
        split2(a, b, h, l);
        H[i] = h; L[i] = l;
    }
}

// ---------------- KNN + interpolation + concat -> split bf16 feat ----------------
#define NXC 2048
__global__ __launch_bounds__(256)
void knn_interp_kernel(const float* __restrict__ yp, const float* __restrict__ yf,
                       const float* __restrict__ xp, const float* __restrict__ xf,
                       uint32_t* __restrict__ featH, uint32_t* __restrict__ featL)
{
    __shared__ float4 s_pt[NXC];
    int b = blockIdx.y;
    int tid = threadIdx.x;
    int n = blockIdx.x * 256 + tid;
    int m = b * NY + n;

    const float* xpb = xp + (size_t)b * NX * 3;
    float px = yp[(size_t)m * 3 + 0];
    float py = yp[(size_t)m * 3 + 1];
    float pz = yp[(size_t)m * 3 + 2];
    float psq = __fadd_rn(__fadd_rn(__fmul_rn(px, px), __fmul_rn(py, py)),
                          __fmul_rn(pz, pz));

    float d0 = 3.4e38f, d1 = 3.4e38f, d2 = 3.4e38f;
    int i0 = 0, i1 = 0, i2 = 0;

    for (int ch = 0; ch < NX; ch += NXC) {
        __syncthreads();
        for (int j = tid; j < NXC; j += 256) {
            const float* xq = xpb + 3 * (size_t)(ch + j);
            float x = xq[0], y = xq[1], z = xq[2];
            float xsq = __fadd_rn(__fadd_rn(__fmul_rn(x, x), __fmul_rn(y, y)),
                                  __fmul_rn(z, z));
            s_pt[j] = make_float4(x, y, z, xsq);
        }
        __syncthreads();
        #pragma unroll 8
        for (int j = 0; j < NXC; j++) {
            float4 q = s_pt[j];
            float dot = __fmaf_rn(pz, q.z, __fmaf_rn(py, q.y, __fmul_rn(px, q.x)));
            float d = __fsub_rn(__fadd_rn(psq, q.w), __fmul_rn(2.0f, dot));
            if (d < d2) {
                int jj = ch + j;
                if (d < d1) {
                    d2 = d1; i2 = i1;
                    if (d < d0) { d1 = d0; i1 = i0; d0 = d; i0 = jj; }
                    else        { d1 = d;  i1 = jj; }
                } else { d2 = d; i2 = jj; }
            }
        }
    }

    float w0 = 1.0f / (d0 + IEPS);
    float w1 = 1.0f / (d1 + IEPS);
    float w2 = 1.0f / (d2 + IEPS);
    float ws = 1.0f / (w0 + w1 + w2);
    w0 *= ws; w1 *= ws; w2 *= ws;

    int lane = tid & 31;
    const float* xfb = xf + (size_t)b * NX * CX;
    unsigned mask = 0xffffffffu;
    for (int s = 0; s < 32; s++) {
        int   j0 = __shfl_sync(mask, i0, s);
        int   j1 = __shfl_sync(mask, i1, s);
        int   j2 = __shfl_sync(mask, i2, s);
        float a0 = __shfl_sync(mask, w0, s);
        float a1 = __shfl_sync(mask, w1, s);
        float a2 = __shfl_sync(mask, w2, s);
        int ms = m - lane + s;
        uint32_t* hrow = featH + (size_t)ms * DIMW;
        uint32_t* lrow = featL + (size_t)ms * DIMW;
        // y_feats: float4 per lane -> 2 words
        const float4* ysrc = (const float4*)(yf + (size_t)ms * CY);
        float4 yv = ysrc[lane];
        uint32_t h0, l0, h1, l1;
        split2(yv.x, yv.y, h0, l0);
        split2(yv.z, yv.w, h1, l1);
        ((uint2*)hrow)[lane] = make_uint2(h0, h1);
        ((uint2*)lrow)[lane] = make_uint2(l0, l1);
        // interpolated x_feats: 2 float4 per lane -> 4 words at offset 64 words
        const float4* r0 = (const float4*)(xfb + (size_t)j0 * CX);
        const float4* r1 = (const float4*)(xfb + (size_t)j1 * CX);
        const float4* r2 = (const float4*)(xfb + (size_t)j2 * CX);
        #pragma unroll
        for (int h = 0; h < 2; h++) {
            int c4 = h * 32 + lane;
            float4 v0 = r0[c4], v1 = r1[c4], v2 = r2[c4];
            float4 o;
            o.x = a0 * v0.x + a1 * v1.x + a2 * v2.x;
            o.y = a0 * v0.y + a1 * v1.y + a2 * v2.y;
            o.z = a0 * v0.z + a1 * v1.z + a2 * v2.z;
            o.w = a0 * v0.w + a1 * v1.w + a2 * v2.w;
            uint32_t oh0, ol0, oh1, ol1;
            split2(o.x, o.y, oh0, ol0);
            split2(o.z, o.w, oh1, ol1);
            ((uint2*)(hrow + 64))[c4] = make_uint2(oh0, oh1);
            ((uint2*)(lrow + 64))[c4] = make_uint2(ol0, ol1);
        }
    }
}

// ---------------- mma.sync 3xBF16 GEMM + fused BN stats ----------------
// NORM=false: A pre-split (AH/AL word arrays). NORM=true: A fp32 + affine+relu+split in stage.
// B always pre-split (BH/BL). Block tile 128x128x16, 8 warps (2m x 4n), warp tile 64x32.
#define SROW_W 12
#define ABUF_W (128 * SROW_W)        // 1536 words
#define BUFF_W (4 * ABUF_W)          // 6144 words per buffer
#define GEMM_SMEM (2 * BUFF_W * 4)   // 49152 bytes

template<bool NORM>
__global__ __launch_bounds__(256)
void mma_gemm_kernel(const uint32_t* __restrict__ AH, const uint32_t* __restrict__ AL,
                     const float* __restrict__ Afp,
                     const uint32_t* __restrict__ BH, const uint32_t* __restrict__ BL,
                     const float* __restrict__ bias,
                     const float* __restrict__ scale, const float* __restrict__ shift,
                     float* __restrict__ Cmat,
                     float* __restrict__ gsum, float* __restrict__ gsq,
                     int Kdim, int Ndim)
{
    extern __shared__ uint32_t smw[];
    const int tid = threadIdx.x;
    const int w = tid >> 5, lane = tid & 31;
    const int m0 = blockIdx.y * 128, n0 = blockIdx.x * 128;
    const int Kw = Kdim >> 1;

    const int aRow = tid >> 1;       // staging row 0..127
    const int half = tid & 1;
    const int sOffW = aRow * SROW_W + half * 4;

    const uint32_t* AHp = NORM ? nullptr : AH + (size_t)(m0 + aRow) * Kw + half * 4;
    const uint32_t* ALp = NORM ? nullptr : AL + (size_t)(m0 + aRow) * Kw + half * 4;
    const float*    Ap  = NORM ? Afp + (size_t)(m0 + aRow) * Kdim + half * 8 : nullptr;
    const uint32_t* BHp = BH + (size_t)(n0 + aRow) * Kw + half * 4;
    const uint32_t* BLp = BL + (size_t)(n0 + aRow) * Kw + half * 4;

    const int nch = Kdim >> 4;

    float acc[4][4][4];
    #pragma unroll
    for (int i = 0; i < 4; i++)
        #pragma unroll
        for (int j = 0; j < 4; j++)
            #pragma unroll
            for (int e = 0; e < 4; e++) acc[i][j][e] = 0.0f;

    uint4 rAH, rAL, rBH, rBL;
    float4 ra0, ra1;

    auto loadc = [&](int c) {
        if (NORM) {
            ra0 = *(const float4*)(Ap + c * 16);
            ra1 = *(const float4*)(Ap + c * 16 + 4);
        } else {
            rAH = *(const uint4*)(AHp + c * 8);
            rAL = *(const uint4*)(ALp + c * 8);
        }
        rBH = *(const uint4*)(BHp + c * 8);
        rBL = *(const uint4*)(BLp + c * 8);
    };
    auto storec = [&](int buf, int kc) {
        uint32_t* S = smw + buf * BUFF_W;
        if (NORM) {
            float av[8] = {ra0.x, ra0.y, ra0.z, ra0.w, ra1.x, ra1.y, ra1.z, ra1.w};
            const float* scp = scale + kc * 16 + half * 8;
            const float* shp = shift + kc * 16 + half * 8;
            #pragma unroll
            for (int j = 0; j < 8; j++)
                av[j] = fmaxf(fmaf(scp[j], av[j], shp[j]), 0.0f);
            uint32_t hw[4], lw[4];
            #pragma unroll
            for (int p = 0; p < 4; p++) split2(av[2 * p], av[2 * p + 1], hw[p], lw[p]);
            *(uint4*)(S + sOffW)          = make_uint4(hw[0], hw[1], hw[2], hw[3]);
            *(uint4*)(S + ABUF_W + sOffW) = make_uint4(lw[0], lw[1], lw[2], lw[3]);
        } else {
            *(uint4*)(S + sOffW)          = rAH;
            *(uint4*)(S + ABUF_W + sOffW) = rAL;
        }
        *(uint4*)(S + 2 * ABUF_W + sOffW) = rBH;
        *(uint4*)(S + 3 * ABUF_W + sOffW) = rBL;
    };

    loadc(0);
    storec(0, 0);
    __syncthreads();

    const int mtb = (w & 1) * 64;
    const int ntb = (w >> 1) * 32;
    const int fr = lane >> 2;
    const int fc = lane & 3;

    for (int c = 0; c < nch; c++) {
        const uint32_t* S = smw + (c & 1) * BUFF_W;
        if (c + 1 < nch) loadc(c + 1);

        uint32_t aHf[4][4], aLf[4][4], bHf[4][2], bLf[4][2];
        #pragma unroll
        for (int i = 0; i < 4; i++) {
            const uint32_t* pa = S + (mtb + i * 16 + fr) * SROW_W + fc;
            aHf[i][0] = pa[0];
            aHf[i][1] = pa[8 * SROW_W];
            aHf[i][2] = pa[4];
            aHf[i][3] = pa[8 * SROW_W + 4];
        }
        #pragma unroll
        for (int j = 0; j < 4; j++) {
            const uint32_t* pb = S + 2 * ABUF_W + (ntb + j * 8 + fr) * SROW_W + fc;
            bHf[j][0] = pb[0];
            bHf[j][1] = pb[4];
        }
        #pragma unroll
        for (int i = 0; i < 4; i++)
            #pragma unroll
            for (int j = 0; j < 4; j++)
                mma16(acc[i][j], aHf[i], bHf[j]);
        #pragma unroll
        for (int j = 0; j < 4; j++) {
            const uint32_t* pb = S + 3 * ABUF_W + (ntb + j * 8 + fr) * SROW_W + fc;
            bLf[j][0] = pb[0];
            bLf[j][1] = pb[4];
        }
        #pragma unroll
        for (int i = 0; i < 4; i++)
            #pragma unroll
            for (int j = 0; j < 4; j++)
                mma16(acc[i][j], aHf[i], bLf[j]);
        #pragma unroll
        for (int i = 0; i < 4; i++) {
            const uint32_t* pa = S + ABUF_W + (mtb + i * 16 + fr) * SROW_W + fc;
            aLf[i][0] = pa[0];
            aLf[i][1] = pa[8 * SROW_W];
            aLf[i][2] = pa[4];
            aLf[i][3] = pa[8 * SROW_W + 4];
        }
        #pragma unroll
        for (int i = 0; i < 4; i++)
            #pragma unroll
            for (int j = 0; j < 4; j++)
                mma16(acc[i][j], aLf[i], bHf[j]);

        if (c + 1 < nch) storec((c + 1) & 1, c + 1);
        __syncthreads();
    }

    // Epilogue: write C (+bias) and accumulate per-column sum/sumsq.
    const int er = m0 + mtb + fr;
    const int ec = n0 + ntb + fc * 2;
    #pragma unroll
    for (int j = 0; j < 4; j++) {
        int cc = ec + j * 8;
        float2 b2 = *(const float2*)(bias + cc);
        float s0 = 0.f, s1 = 0.f, q0 = 0.f, q1 = 0.f;
        #pragma unroll
        for (int i = 0; i < 4; i++) {
            int r = er + i * 16;
            float o00 = acc[i][j][0] + b2.x, o01 = acc[i][j][1] + b2.y;
            float o10 = acc[i][j][2] + b2.x, o11 = acc[i][j][3] + b2.y;
            *(float2*)(Cmat + (size_t)r * Ndim + cc)       = make_float2(o00, o01);
            *(float2*)(Cmat + (size_t)(r + 8) * Ndim + cc) = make_float2(o10, o11);
            s0 += o00 + o10; s1 += o01 + o11;
            q0 += o00 * o00 + o10 * o10;
            q1 += o01 * o01 + o11 * o11;
        }
        #pragma unroll
        for (int off = 4; off < 32; off <<= 1) {
            s0 += __shfl_xor_sync(0xffffffffu, s0, off);
            s1 += __shfl_xor_sync(0xffffffffu, s1, off);
            q0 += __shfl_xor_sync(0xffffffffu, q0, off);
            q1 += __shfl_xor_sync(0xffffffffu, q1, off);
        }
        if (fr == 0) {
            atomicAdd(&gsum[cc], s0);
            atomicAdd(&gsum[cc + 1], s1);
            atomicAdd(&gsq[cc], q0);
            atomicAdd(&gsq[cc + 1], q1);
        }
    }
}

// ---------------- finalize BN affine ----------------
__global__ void finalize_kernel(const float* __restrict__ sum, const float* __restrict__ sq,
                                const float* __restrict__ g, const float* __restrict__ be,
                                float* __restrict__ scale, float* __restrict__ shift, int Cdim)
{
    int c = blockIdx.x * blockDim.x + threadIdx.x;
    if (c < Cdim) {
        const float invM = 1.0f / (float)MTOT;
        float mean = sum[c] * invM;
        float var  = sq[c] * invM - mean * mean;
        float inv  = rsqrtf(var + BN_EPS);
        float sc   = g[c] * inv;
        scale[c] = sc;
        shift[c] = be[c] - mean * sc;
    }
}

// ---------------- final: normalize+relu layer3 and transpose to [B, C3, NY] ----------------
__global__ __launch_bounds__(256)
void trans_norm_kernel(const float* __restrict__ z3, const float* __restrict__ sc,
                       const float* __restrict__ sh, float* __restrict__ out)
{
    __shared__ float tile[32][33];
    int m0 = blockIdx.x * 32;
    int c0 = blockIdx.y * 32;
    int tx = threadIdx.x, ty = threadIdx.y;
    #pragma unroll
    for (int r = ty; r < 32; r += 8) {
        int c = c0 + tx;
        float v = z3[(size_t)(m0 + r) * C3 + c];
        v = fmaxf(fmaf(sc[c], v, sh[c]), 0.0f);
        tile[r][tx] = v;
    }
    __syncthreads();
    int b = m0 / NY;
    int n0 = m0 - b * NY;
    #pragma unroll
    for (int r = ty; r < 32; r += 8) {
        out[((size_t)b * C3 + c0 + r) * NY + n0 + tx] = tile[tx][r];
    }
}

// ---------------- launch ----------------
extern "C" void kernel_launch(void* const* d_in, const int* in_sizes, int n_in,
                              void* d_out, int out_size)
{
    const float* y_points = (const float*)d_in[0];
    const float* y_feats  = (const float*)d_in[1];
    const float* x_points = (const float*)d_in[2];
    const float* x_feats  = (const float*)d_in[3];
    const float* W1 = (const float*)d_in[4];
    const float* b1 = (const float*)d_in[5];
    const float* g1 = (const float*)d_in[6];
    const float* be1 = (const float*)d_in[7];
    const float* W2 = (const float*)d_in[8];
    const float* b2 = (const float*)d_in[9];
    const float* g2 = (const float*)d_in[10];
    const float* be2 = (const float*)d_in[11];
    const float* W3 = (const float*)d_in[12];
    const float* b3 = (const float*)d_in[13];
    const float* g3 = (const float*)d_in[14];
    const float* be3 = (const float*)d_in[15];
    float* out = (float*)d_out;

    uint32_t *featH, *featL, *w1h, *w1l, *w2h, *w2l, *w3h, *w3l;
    float *z1, *z2, *z3, *red, *aff;
    cudaGetSymbolAddress((void**)&featH, g_featH);
    cudaGetSymbolAddress((void**)&featL, g_featL);
    cudaGetSymbolAddress((void**)&z1, g_z1);
    cudaGetSymbolAddress((void**)&z2, g_z2);
    cudaGetSymbolAddress((void**)&z3, g_z3);
    cudaGetSymbolAddress((void**)&red, g_red);
    cudaGetSymbolAddress((void**)&aff, g_aff);
    cudaGetSymbolAddress((void**)&w1h, g_w1h);
    cudaGetSymbolAddress((void**)&w1l, g_w1l);
    cudaGetSymbolAddress((void**)&w2h, g_w2h);
    cudaGetSymbolAddress((void**)&w2l, g_w2l);
    cudaGetSymbolAddress((void**)&w3h, g_w3h);
    cudaGetSymbolAddress((void**)&w3l, g_w3l);

    float* sum1 = red + 0;    float* sq1 = red + 512;
    float* sum2 = red + 1024; float* sq2 = red + 1280;
    float* sum3 = red + 1536; float* sq3 = red + 1664;
    float* sc1 = aff + 0;     float* sh1 = aff + 512;
    float* sc2 = aff + 1024;  float* sh2 = aff + 1280;
    float* sc3 = aff + 1536;  float* sh3 = aff + 1664;

    cudaFuncSetAttribute(mma_gemm_kernel<false>, cudaFuncAttributeMaxDynamicSharedMemorySize, GEMM_SMEM);
    cudaFuncSetAttribute(mma_gemm_kernel<true>,  cudaFuncAttributeMaxDynamicSharedMemorySize, GEMM_SMEM);

    zero_kernel<<<7, 256>>>(red, 1792);
    split_w_kernel<<<(C1 * DIMF / 2 + 255) / 256, 256>>>(W1, w1h, w1l, C1 * DIMF / 2);
    split_w_kernel<<<(C2 * C1 / 2 + 255) / 256, 256>>>(W2, w2h, w2l, C2 * C1 / 2);
    split_w_kernel<<<(C3 * C2 / 2 + 255) / 256, 256>>>(W3, w3h, w3l, C3 * C2 / 2);

    knn_interp_kernel<<<dim3(NY / 256, BATCH), 256>>>(y_points, y_feats, x_points, x_feats, featH, featL);

    mma_gemm_kernel<false><<<dim3(C1 / 128, MTOT / 128), 256, GEMM_SMEM>>>(
        featH, featL, nullptr, w1h, w1l, b1, nullptr, nullptr, z1, sum1, sq1, DIMF, C1);
    finalize_kernel<<<2, 256>>>(sum1, sq1, g1, be1, sc1, sh1, C1);

    mma_gemm_kernel<true><<<dim3(C2 / 128, MTOT / 128), 256, GEMM_SMEM>>>(
        nullptr, nullptr, z1, w2h, w2l, b2, sc1, sh1, z2, sum2, sq2, C1, C2);
    finalize_kernel<<<1, 256>>>(sum2, sq2, g2, be2, sc2, sh2, C2);

    mma_gemm_kernel<true><<<dim3(C3 / 128, MTOT / 128), 256, GEMM_SMEM>>>(
        nullptr, nullptr, z2, w3h, w3l, b3, sc2, sh2, z3, sum3, sq3, C2, C3);
    finalize_kernel<<<1, 128>>>(sum3, sq3, g3, be3, sc3, sh3, C3);

    trans_norm_kernel<<<dim3(MTOT / 32, C3 / 32), dim3(32, 8)>>>(z3, sc3, sh3, out);
}

// round 8
// speedup vs baseline: 1.1049x; 1.1049x over previous
#include <cuda_runtime.h>
#include <cuda_bf16.h>
#include <cstdint>

// Problem constants
#define BATCH 4
#define NY 16384
#define NX 4096
#define CY 128
#define CX 256
#define DIMF 384       // CY + CX
#define C1 512
#define C2 256
#define C3 128
#define MTOT (BATCH*NY)   // 65536
#define IEPS 1e-8f
#define BN_EPS 1e-5f

// ---------------- scratch (device globals; no runtime alloc) ----------------
__device__ float g_feat[(size_t)MTOT * DIMF];
__device__ float g_z1[(size_t)MTOT * C1];
__device__ float g_z2[(size_t)MTOT * C2];
__device__ float g_z3[(size_t)MTOT * C3];
__device__ float g_red[1792];
__device__ float g_aff[1792];
// pre-split weights (bf16x2 words, row-major [N][K/2])
__device__ uint32_t g_w1h[C1 * DIMF / 2], g_w1l[C1 * DIMF / 2];
__device__ uint32_t g_w2h[C2 * C1 / 2],  g_w2l[C2 * C1 / 2];
__device__ uint32_t g_w3h[C3 * C2 / 2],  g_w3l[C3 * C2 / 2];

// pack two floats to bf16x2 (a -> low half, b -> high half)
__device__ __forceinline__ uint32_t cvt2bf(float lo, float hi) {
    uint32_t r;
    asm("cvt.rn.bf16x2.f32 %0, %1, %2;" : "=r"(r) : "f"(hi), "f"(lo));
    return r;
}
__device__ __forceinline__ void split2(float a, float b, uint32_t& h, uint32_t& l) {
    h = cvt2bf(a, b);
    float h0 = __uint_as_float(h << 16);
    float h1 = __uint_as_float(h & 0xffff0000u);
    l = cvt2bf(a - h0, b - h1);
}

// m16n8k16 BF16 mma
__device__ __forceinline__ void mma16(float* c, const uint32_t* a, const uint32_t* b) {
    asm volatile(
        "mma.sync.aligned.m16n8k16.row.col.f32.bf16.bf16.f32 "
        "{%0,%1,%2,%3}, {%4,%5,%6,%7}, {%8,%9}, {%0,%1,%2,%3};"
        : "+f"(c[0]), "+f"(c[1]), "+f"(c[2]), "+f"(c[3])
        : "r"(a[0]), "r"(a[1]), "r"(a[2]), "r"(a[3]),
          "r"(b[0]), "r"(b[1]));
}
#define LDSM4(r0, r1, r2, r3, addr) \
    asm volatile("ldmatrix.sync.aligned.m8n8.x4.shared.b16 {%0,%1,%2,%3}, [%4];" \
        : "=r"(r0), "=r"(r1), "=r"(r2), "=r"(r3) : "r"(addr))
#define CPASYNC16(dst, src) \
    asm volatile("cp.async.cg.shared.global [%0], [%1], 16;" :: "r"(dst), "l"(src))
#define CPCOMMIT()  asm volatile("cp.async.commit_group;" ::: "memory")
#define CPWAIT0()   asm volatile("cp.async.wait_group 0;" ::: "memory")

__device__ __forceinline__ uint32_t smem_u32(const void* p) {
    uint32_t a;
    asm("{ .reg .u64 t; cvta.to.shared.u64 t, %1; cvt.u32.u64 %0, t; }" : "=r"(a) : "l"(p));
    return a;
}

// ---------------- zero kernel ----------------
__global__ void zero_kernel(float* __restrict__ p, int n) {
    int i = blockIdx.x * blockDim.x + threadIdx.x;
    if (i < n) p[i] = 0.0f;
}

// ---------------- weight split prep ----------------
__global__ void split_w_kernel(const float* __restrict__ W,
                               uint32_t* __restrict__ H, uint32_t* __restrict__ L, int nwords) {
    int i = blockIdx.x * blockDim.x + threadIdx.x;
    if (i < nwords) {
        uint32_t h, l;
        split2(W[2 * i], W[2 * i + 1], h, l);
        H[i] = h; L[i] = l;
    }
}

// ---------------- KNN + interpolation + concat (exact fp32 op-tree) ----------------
#define NXC 2048
__global__ __launch_bounds__(256)
void knn_interp_kernel(const float* __restrict__ yp, const float* __restrict__ yf,
                       const float* __restrict__ xp, const float* __restrict__ xf,
                       float* __restrict__ feat)
{
    __shared__ float4 s_pt[NXC];
    int b = blockIdx.y;
    int tid = threadIdx.x;
    int n = blockIdx.x * 256 + tid;
    int m = b * NY + n;

    const float* xpb = xp + (size_t)b * NX * 3;
    float px = yp[(size_t)m * 3 + 0];
    float py = yp[(size_t)m * 3 + 1];
    float pz = yp[(size_t)m * 3 + 2];
    float psq = __fadd_rn(__fadd_rn(__fmul_rn(px, px), __fmul_rn(py, py)),
                          __fmul_rn(pz, pz));

    float d0 = 3.4e38f, d1 = 3.4e38f, d2 = 3.4e38f;
    int i0 = 0, i1 = 0, i2 = 0;

    for (int ch = 0; ch < NX; ch += NXC) {
        __syncthreads();
        for (int j = tid; j < NXC; j += 256) {
            const float* xq = xpb + 3 * (size_t)(ch + j);
            float x = xq[0], y = xq[1], z = xq[2];
            float xsq = __fadd_rn(__fadd_rn(__fmul_rn(x, x), __fmul_rn(y, y)),
                                  __fmul_rn(z, z));
            s_pt[j] = make_float4(x, y, z, xsq);
        }
        __syncthreads();
        #pragma unroll 8
        for (int j = 0; j < NXC; j++) {
            float4 q = s_pt[j];
            float dot = __fmaf_rn(pz, q.z, __fmaf_rn(py, q.y, __fmul_rn(px, q.x)));
            float d = __fsub_rn(__fadd_rn(psq, q.w), __fmul_rn(2.0f, dot));
            if (d < d2) {
                int jj = ch + j;
                if (d < d1) {
                    d2 = d1; i2 = i1;
                    if (d < d0) { d1 = d0; i1 = i0; d0 = d; i0 = jj; }
                    else        { d1 = d;  i1 = jj; }
                } else { d2 = d; i2 = jj; }
            }
        }
    }

    float w0 = 1.0f / (d0 + IEPS);
    float w1 = 1.0f / (d1 + IEPS);
    float w2 = 1.0f / (d2 + IEPS);
    float ws = 1.0f / (w0 + w1 + w2);
    w0 *= ws; w1 *= ws; w2 *= ws;

    int lane = tid & 31;
    const float* xfb = xf + (size_t)b * NX * CX;
    unsigned mask = 0xffffffffu;
    for (int s = 0; s < 32; s++) {
        int   j0 = __shfl_sync(mask, i0, s);
        int   j1 = __shfl_sync(mask, i1, s);
        int   j2 = __shfl_sync(mask, i2, s);
        float a0 = __shfl_sync(mask, w0, s);
        float a1 = __shfl_sync(mask, w1, s);
        float a2 = __shfl_sync(mask, w2, s);
        int ms = m - lane + s;
        float* frow = feat + (size_t)ms * DIMF;
        const float4* ysrc = (const float4*)(yf + (size_t)ms * CY);
        ((float4*)frow)[lane] = ysrc[lane];
        const float4* r0 = (const float4*)(xfb + (size_t)j0 * CX);
        const float4* r1 = (const float4*)(xfb + (size_t)j1 * CX);
        const float4* r2 = (const float4*)(xfb + (size_t)j2 * CX);
        float4* dst = (float4*)(frow + CY);
        #pragma unroll
        for (int h = 0; h < 2; h++) {
            int c4 = h * 32 + lane;
            float4 v0 = r0[c4], v1 = r1[c4], v2 = r2[c4];
            float4 o;
            o.x = a0 * v0.x + a1 * v1.x + a2 * v2.x;
            o.y = a0 * v0.y + a1 * v1.y + a2 * v2.y;
            o.z = a0 * v0.z + a1 * v1.z + a2 * v2.z;
            o.w = a0 * v0.w + a1 * v1.w + a2 * v2.w;
            dst[c4] = o;
        }
    }
}

// ---------------- mma.sync 3xBF16 GEMM + fused BN stats ----------------
// A: fp32 (optional BN-affine+relu), split hi/lo at smem-store.
// B: pre-split bf16x2 hi/lo, staged via cp.async (pure copy, overlapped).
// Fragments loaded with ldmatrix.x4. Block 128x128x16, 8 warps (2m x 4n).
#define SROW_W 12
#define ABUF_W (128 * SROW_W)        // 1536 words
#define BUFF_W (4 * ABUF_W)          // 6144 words per buffer
#define GEMM_SMEM (2 * BUFF_W * 4)   // 49152 bytes

template<bool NORM>
__global__ __launch_bounds__(256)
void mma_gemm_kernel(const float* __restrict__ Afp,
                     const uint32_t* __restrict__ BH, const uint32_t* __restrict__ BL,
                     const float* __restrict__ bias,
                     const float* __restrict__ scale, const float* __restrict__ shift,
                     float* __restrict__ Cmat,
                     float* __restrict__ gsum, float* __restrict__ gsq,
                     int Kdim, int Ndim)
{
    extern __shared__ uint32_t smw[];
    const uint32_t sbase = smem_u32(smw);
    const int tid = threadIdx.x;
    const int w = tid >> 5, lane = tid & 31;
    const int m0 = blockIdx.y * 128, n0 = blockIdx.x * 128;
    const int Kw = Kdim >> 1;

    const int aRow = tid >> 1;       // staging row 0..127
    const int half = tid & 1;
    const int sOffW = aRow * SROW_W + half * 4;

    const float*    Ap  = Afp + (size_t)(m0 + aRow) * Kdim + half * 8;
    const uint32_t* BHp = BH + (size_t)(n0 + aRow) * Kw + half * 4;
    const uint32_t* BLp = BL + (size_t)(n0 + aRow) * Kw + half * 4;

    const int nch = Kdim >> 4;

    float acc[4][4][4];
    #pragma unroll
    for (int i = 0; i < 4; i++)
        #pragma unroll
        for (int j = 0; j < 4; j++)
            #pragma unroll
            for (int e = 0; e < 4; e++) acc[i][j][e] = 0.0f;

    float4 ra0, ra1;

    auto issueB = [&](int buf, int c) {
        uint32_t dh = sbase + 4u * (buf * BUFF_W + 2 * ABUF_W + sOffW);
        uint32_t dl = sbase + 4u * (buf * BUFF_W + 3 * ABUF_W + sOffW);
        CPASYNC16(dh, BHp + c * 8);
        CPASYNC16(dl, BLp + c * 8);
    };
    auto loadA = [&](int c) {
        ra0 = *(const float4*)(Ap + c * 16);
        ra1 = *(const float4*)(Ap + c * 16 + 4);
    };
    auto storeA = [&](int buf, int kc) {
        uint32_t* S = smw + buf * BUFF_W;
        float av[8] = {ra0.x, ra0.y, ra0.z, ra0.w, ra1.x, ra1.y, ra1.z, ra1.w};
        if (NORM) {
            const float* scp = scale + kc * 16 + half * 8;
            const float* shp = shift + kc * 16 + half * 8;
            #pragma unroll
            for (int j = 0; j < 8; j++)
                av[j] = fmaxf(fmaf(scp[j], av[j], shp[j]), 0.0f);
        }
        uint32_t hw[4], lw[4];
        #pragma unroll
        for (int p = 0; p < 4; p++) split2(av[2 * p], av[2 * p + 1], hw[p], lw[p]);
        *(uint4*)(S + sOffW)          = make_uint4(hw[0], hw[1], hw[2], hw[3]);
        *(uint4*)(S + ABUF_W + sOffW) = make_uint4(lw[0], lw[1], lw[2], lw[3]);
    };

    // prologue: chunk 0 into buf 0
    issueB(0, 0);
    loadA(0);
    storeA(0, 0);
    CPCOMMIT();
    CPWAIT0();
    __syncthreads();

    const int mtb = (w & 1) * 64;
    const int ntb = (w >> 1) * 32;
    const int fr = lane >> 2;
    const int fc = lane & 3;

    // ldmatrix per-lane address components
    const int rA = mtb + ((lane >> 3) & 1) * 8 + (lane & 7);   // + i*16
    const int wA = (lane >> 4) * 4;
    const int rB = ntb + (lane >> 4) * 8 + (lane & 7);          // + j2*16
    const int wB = ((lane >> 3) & 1) * 4;

    for (int c = 0; c < nch; c++) {
        const int buf = c & 1;
        const uint32_t soff = sbase + 4u * (buf * BUFF_W);
        if (c + 1 < nch) {
            issueB(buf ^ 1, c + 1);
            CPCOMMIT();
            loadA(c + 1);
        }

        uint32_t aF[4][4], bF[4][2];
        // A-hi fragments (4 x ldmatrix.x4)
        #pragma unroll
        for (int i = 0; i < 4; i++) {
            uint32_t ad = soff + 4u * ((uint32_t)(rA + i * 16) * SROW_W + wA);
            LDSM4(aF[i][0], aF[i][1], aF[i][2], aF[i][3], ad);
        }
        // B-hi fragments (2 x ldmatrix.x4 covering j=0..3)
        #pragma unroll
        for (int j2 = 0; j2 < 2; j2++) {
            uint32_t ad = soff + 4u * (2 * ABUF_W + (uint32_t)(rB + j2 * 16) * SROW_W + wB);
            LDSM4(bF[2 * j2][0], bF[2 * j2][1], bF[2 * j2 + 1][0], bF[2 * j2 + 1][1], ad);
        }
        #pragma unroll
        for (int i = 0; i < 4; i++)
            #pragma unroll
            for (int j = 0; j < 4; j++)
                mma16(acc[i][j], aF[i], bF[j]);
        // B-lo
        #pragma unroll
        for (int j2 = 0; j2 < 2; j2++) {
            uint32_t ad = soff + 4u * (3 * ABUF_W + (uint32_t)(rB + j2 * 16) * SROW_W + wB);
            LDSM4(bF[2 * j2][0], bF[2 * j2][1], bF[2 * j2 + 1][0], bF[2 * j2 + 1][1], ad);
        }
        #pragma unroll
        for (int i = 0; i < 4; i++)
            #pragma unroll
            for (int j = 0; j < 4; j++)
                mma16(acc[i][j], aF[i], bF[j]);
        // A-lo (overwrite aF), then Al*Bl-hi? no: Al x Bh
        #pragma unroll
        for (int i = 0; i < 4; i++) {
            uint32_t ad = soff + 4u * (ABUF_W + (uint32_t)(rA + i * 16) * SROW_W + wA);
            LDSM4(aF[i][0], aF[i][1], aF[i][2], aF[i][3], ad);
        }
        // reload B-hi
        #pragma unroll
        for (int j2 = 0; j2 < 2; j2++) {
            uint32_t ad = soff + 4u * (2 * ABUF_W + (uint32_t)(rB + j2 * 16) * SROW_W + wB);
            LDSM4(bF[2 * j2][0], bF[2 * j2][1], bF[2 * j2 + 1][0], bF[2 * j2 + 1][1], ad);
        }
        #pragma unroll
        for (int i = 0; i < 4; i++)
            #pragma unroll
            for (int j = 0; j < 4; j++)
                mma16(acc[i][j], aF[i], bF[j]);

        if (c + 1 < nch) {
            storeA(buf ^ 1, c + 1);
            CPWAIT0();
        }
        __syncthreads();
    }

    // Epilogue: write C (+bias) and accumulate per-column sum/sumsq.
    const int er = m0 + mtb + fr;
    const int ec = n0 + ntb + fc * 2;
    #pragma unroll
    for (int j = 0; j < 4; j++) {
        int cc = ec + j * 8;
        float2 b2 = *(const float2*)(bias + cc);
        float s0 = 0.f, s1 = 0.f, q0 = 0.f, q1 = 0.f;
        #pragma unroll
        for (int i = 0; i < 4; i++) {
            int r = er + i * 16;
            float o00 = acc[i][j][0] + b2.x, o01 = acc[i][j][1] + b2.y;
            float o10 = acc[i][j][2] + b2.x, o11 = acc[i][j][3] + b2.y;
            *(float2*)(Cmat + (size_t)r * Ndim + cc)       = make_float2(o00, o01);
            *(float2*)(Cmat + (size_t)(r + 8) * Ndim + cc) = make_float2(o10, o11);
            s0 += o00 + o10; s1 += o01 + o11;
            q0 += o00 * o00 + o10 * o10;
            q1 += o01 * o01 + o11 * o11;
        }
        #pragma unroll
        for (int off = 4; off < 32; off <<= 1) {
            s0 += __shfl_xor_sync(0xffffffffu, s0, off);
            s1 += __shfl_xor_sync(0xffffffffu, s1, off);
            q0 += __shfl_xor_sync(0xffffffffu, q0, off);
            q1 += __shfl_xor_sync(0xffffffffu, q1, off);
        }
        if (fr == 0) {
            atomicAdd(&gsum[cc], s0);
            atomicAdd(&gsum[cc + 1], s1);
            atomicAdd(&gsq[cc], q0);
            atomicAdd(&gsq[cc + 1], q1);
        }
    }
}

// ---------------- finalize BN affine ----------------
__global__ void finalize_kernel(const float* __restrict__ sum, const float* __restrict__ sq,
                                const float* __restrict__ g, const float* __restrict__ be,
                                float* __restrict__ scale, float* __restrict__ shift, int Cdim)
{
    int c = blockIdx.x * blockDim.x + threadIdx.x;
    if (c < Cdim) {
        const float invM = 1.0f / (float)MTOT;
        float mean = sum[c] * invM;
        float var  = sq[c] * invM - mean * mean;
        float inv  = rsqrtf(var + BN_EPS);
        float sc   = g[c] * inv;
        scale[c] = sc;
        shift[c] = be[c] - mean * sc;
    }
}

// ---------------- final: normalize+relu layer3 and transpose to [B, C3, NY] ----------------
__global__ __launch_bounds__(256)
void trans_norm_kernel(const float* __restrict__ z3, const float* __restrict__ sc,
                       const float* __restrict__ sh, float* __restrict__ out)
{
    __shared__ float tile[32][33];
    int m0 = blockIdx.x * 32;
    int c0 = blockIdx.y * 32;
    int tx = threadIdx.x, ty = threadIdx.y;
    #pragma unroll
    for (int r = ty; r < 32; r += 8) {
        int c = c0 + tx;
        float v = z3[(size_t)(m0 + r) * C3 + c];
        v = fmaxf(fmaf(sc[c], v, sh[c]), 0.0f);
        tile[r][tx] = v;
    }
    __syncthreads();
    int b = m0 / NY;
    int n0 = m0 - b * NY;
    #pragma unroll
    for (int r = ty; r < 32; r += 8) {
        out[((size_t)b * C3 + c0 + r) * NY + n0 + tx] = tile[tx][r];
    }
}

// ---------------- launch ----------------
extern "C" void kernel_launch(void* const* d_in, const int* in_sizes, int n_in,
                              void* d_out, int out_size)
{
    const float* y_points = (const float*)d_in[0];
    const float* y_feats  = (const float*)d_in[1];
    const float* x_points = (const float*)d_in[2];
    const float* x_feats  = (const float*)d_in[3];
    const float* W1 = (const float*)d_in[4];
    const float* b1 = (const float*)d_in[5];
    const float* g1 = (const float*)d_in[6];
    const float* be1 = (const float*)d_in[7];
    const float* W2 = (const float*)d_in[8];
    const float* b2 = (const float*)d_in[9];
    const float* g2 = (const float*)d_in[10];
    const float* be2 = (const float*)d_in[11];
    const float* W3 = (const float*)d_in[12];
    const float* b3 = (const float*)d_in[13];
    const float* g3 = (const float*)d_in[14];
    const float* be3 = (const float*)d_in[15];
    float* out = (float*)d_out;

    float *feat, *z1, *z2, *z3, *red, *aff;
    uint32_t *w1h, *w1l, *w2h, *w2l, *w3h, *w3l;
    cudaGetSymbolAddress((void**)&feat, g_feat);
    cudaGetSymbolAddress((void**)&z1, g_z1);
    cudaGetSymbolAddress((void**)&z2, g_z2);
    cudaGetSymbolAddress((void**)&z3, g_z3);
    cudaGetSymbolAddress((void**)&red, g_red);
    cudaGetSymbolAddress((void**)&aff, g_aff);
    cudaGetSymbolAddress((void**)&w1h, g_w1h);
    cudaGetSymbolAddress((void**)&w1l, g_w1l);
    cudaGetSymbolAddress((void**)&w2h, g_w2h);
    cudaGetSymbolAddress((void**)&w2l, g_w2l);
    cudaGetSymbolAddress((void**)&w3h, g_w3h);
    cudaGetSymbolAddress((void**)&w3l, g_w3l);

    float* sum1 = red + 0;    float* sq1 = red + 512;
    float* sum2 = red + 1024; float* sq2 = red + 1280;
    float* sum3 = red + 1536; float* sq3 = red + 1664;
    float* sc1 = aff + 0;     float* sh1 = aff + 512;
    float* sc2 = aff + 1024;  float* sh2 = aff + 1280;
    float* sc3 = aff + 1536;  float* sh3 = aff + 1664;

    cudaFuncSetAttribute(mma_gemm_kernel<false>, cudaFuncAttributeMaxDynamicSharedMemorySize, GEMM_SMEM);
    cudaFuncSetAttribute(mma_gemm_kernel<true>,  cudaFuncAttributeMaxDynamicSharedMemorySize, GEMM_SMEM);

    zero_kernel<<<7, 256>>>(red, 1792);
    split_w_kernel<<<(C1 * DIMF / 2 + 255) / 256, 256>>>(W1, w1h, w1l, C1 * DIMF / 2);
    split_w_kernel<<<(C2 * C1 / 2 + 255) / 256, 256>>>(W2, w2h, w2l, C2 * C1 / 2);
    split_w_kernel<<<(C3 * C2 / 2 + 255) / 256, 256>>>(W3, w3h, w3l, C3 * C2 / 2);

    knn_interp_kernel<<<dim3(NY / 256, BATCH), 256>>>(y_points, y_feats, x_points, x_feats, feat);

    mma_gemm_kernel<false><<<dim3(C1 / 128, MTOT / 128), 256, GEMM_SMEM>>>(
        feat, w1h, w1l, b1, nullptr, nullptr, z1, sum1, sq1, DIMF, C1);
    finalize_kernel<<<2, 256>>>(sum1, sq1, g1, be1, sc1, sh1, C1);

    mma_gemm_kernel<true><<<dim3(C2 / 128, MTOT / 128), 256, GEMM_SMEM>>>(
        z1, w2h, w2l, b2, sc1, sh1, z2, sum2, sq2, C1, C2);
    finalize_kernel<<<1, 256>>>(sum2, sq2, g2, be2, sc2, sh2, C2);

    mma_gemm_kernel<true><<<dim3(C3 / 128, MTOT / 128), 256, GEMM_SMEM>>>(
        z2, w3h, w3l, b3, sc2, sh2, z3, sum3, sq3, C2, C3);
    finalize_kernel<<<1, 128>>>(sum3, sq3, g3, be3, sc3, sh3, C3);

    trans_norm_kernel<<<dim3(MTOT / 32, C3 / 32), dim3(32, 8)>>>(z3, sc3, sh3, out);
}